// round 1
// baseline (speedup 1.0000x reference)
#include <cuda_runtime.h>

#define RSPLIT   8
#define ROWS     64            // 512 / RSPLIT rows per CTA
#define NB       160           // 5*32 boxes per batch
#define NTHREADS 256

// Per-(batch, segment) partials: [pred_sum, painted_sigmoid_sum, painted_count, pad]
__device__ float g_part[64][RSPLIT][4];

__device__ __forceinline__ float sigf(float x) {
    // sigmoid(x) = 1 / (1 + e^{-x}); 2 MUFU ops (EX2 + RCP) per element
    float e = __expf(-x);
    return __fdividef(1.0f, 1.0f + e);
}

__global__ void __launch_bounds__(NTHREADS)
mml_main(const float* __restrict__ pred, const int* __restrict__ tgt) {
    const int b    = blockIdx.x;      // batch
    const int seg  = blockIdx.y;      // row segment
    const int row0 = seg * ROWS;
    const int tid  = threadIdx.x;
    const int lane = tid & 31;
    const int warp = tid >> 5;

    __shared__ unsigned mask[ROWS * 16];   // 512 column-bits per row
    __shared__ int4     boxes[NB];
    __shared__ float    red[3][NTHREADS / 32];

    // ---- init mask + load boxes ----
    for (int i = tid; i < ROWS * 16; i += NTHREADS) mask[i] = 0u;
    const int4* tb = (const int4*)(tgt + (size_t)b * NB * 4);
    if (tid < NB) boxes[tid] = tb[tid];
    __syncthreads();

    // ---- paint: warp w handles boxes w, w+8, ...; lanes stride rows ----
    for (int i = warp; i < NB; i += NTHREADS / 32) {
        int4 bx = boxes[i];
        int x1 = min(bx.x, 512), y1 = min(bx.y, 512);
        int x2 = min(bx.x + bx.z, 512), y2 = min(bx.y + bx.w, 512);
        int rs = max(x1, row0), re = min(x2, row0 + ROWS);
        if (rs >= re || y1 >= y2) continue;
        int wlo = y1 >> 5, whi = (y2 - 1) >> 5;
        unsigned loMask = ~((1u << (y1 & 31)) - 1u);
        unsigned hiMask = 0xFFFFFFFFu >> (31 - ((y2 - 1) & 31));
        for (int r = rs + lane; r < re; r += 32) {
            unsigned* mrow = &mask[(r - row0) * 16];
            #pragma unroll 4
            for (int w = wlo; w <= whi; w++) {
                unsigned bits = 0xFFFFFFFFu;
                if (w == wlo) bits &= loMask;
                if (w == whi) bits &= hiMask;
                atomicOr(&mrow[w], bits);
            }
        }
    }
    __syncthreads();

    // ---- streaming reduction over this CTA's 64x512 tile ----
    float psum = 0.f, isum = 0.f, cnt = 0.f;
    const float4* p = (const float4*)(pred + ((size_t)b * 512 + row0) * 512);
    #pragma unroll 4
    for (int idx = tid; idx < ROWS * 128; idx += NTHREADS) {
        int r  = idx >> 7;        // row within segment
        int c4 = idx & 127;       // float4 index within row
        float4 v = p[idx];
        float s0 = sigf(v.x), s1 = sigf(v.y), s2 = sigf(v.z), s3 = sigf(v.w);
        psum += (s0 + s1) + (s2 + s3);
        unsigned mw = mask[r * 16 + (c4 >> 3)] >> ((c4 & 7) * 4);
        if (mw & 1u) { isum += s0; cnt += 1.f; }
        if (mw & 2u) { isum += s1; cnt += 1.f; }
        if (mw & 4u) { isum += s2; cnt += 1.f; }
        if (mw & 8u) { isum += s3; cnt += 1.f; }
    }

    // ---- block reduce (warp shuffle -> smem -> thread 0) ----
    #pragma unroll
    for (int off = 16; off; off >>= 1) {
        psum += __shfl_down_sync(0xffffffffu, psum, off);
        isum += __shfl_down_sync(0xffffffffu, isum, off);
        cnt  += __shfl_down_sync(0xffffffffu, cnt,  off);
    }
    if (lane == 0) { red[0][warp] = psum; red[1][warp] = isum; red[2][warp] = cnt; }
    __syncthreads();
    if (tid == 0) {
        float P = 0.f, I = 0.f, C = 0.f;
        #pragma unroll
        for (int w = 0; w < NTHREADS / 32; w++) {
            P += red[0][w]; I += red[1][w]; C += red[2][w];
        }
        g_part[b][seg][0] = P;
        g_part[b][seg][1] = I;
        g_part[b][seg][2] = C;
    }
}

__global__ void mml_final(float* __restrict__ out) {
    int b = threadIdx.x;           // 64 threads, one per batch
    float P = 0.f, I = 0.f, C = 0.f;
    #pragma unroll
    for (int s = 0; s < RSPLIT; s++) {
        P += g_part[b][s][0]; I += g_part[b][s][1]; C += g_part[b][s][2];
    }
    float inter = 255.f * I;
    float loss  = (inter + 1.f) / (P + 255.f * C - inter + 1.f);
    __shared__ float sh[64];
    sh[b] = loss;
    __syncthreads();
    #pragma unroll
    for (int off = 32; off; off >>= 1) {
        if (b < off) sh[b] += sh[b + off];
        __syncthreads();
    }
    if (b == 0) out[0] = 1.0f - sh[0] * (1.0f / 64.0f);
}

extern "C" void kernel_launch(void* const* d_in, const int* in_sizes, int n_in,
                              void* d_out, int out_size) {
    const float* pred = (const float*)d_in[0];   // (64,1,512,512) fp32
    const int*   tgt  = (const int*)d_in[1];     // (64,5,32,4) int32
    float* out = (float*)d_out;                  // scalar

    dim3 grid(64, RSPLIT);
    mml_main<<<grid, NTHREADS>>>(pred, tgt);
    mml_final<<<1, 64>>>(out);
}

// round 3
// speedup vs baseline: 1.0291x; 1.0291x over previous
#include <cuda_runtime.h>

#define RSPLIT   8
#define ROWS     64            // 512 / RSPLIT rows per CTA
#define NB       160           // 5*32 boxes per batch
#define NT       256
#define NCTAS    (64 * RSPLIT)

// Per-(batch, segment) partials: [pred_sum, painted_sigmoid_sum, painted_count]
__device__ float    g_part[64][RSPLIT][4];
__device__ unsigned g_count = 0;   // last-block-done counter (self-resetting)

__device__ __forceinline__ float sigf(float x) {
    return __fdividef(1.0f, 1.0f + __expf(-x));   // EX2 + RCP: 2 MUFU
}

__global__ void __launch_bounds__(NT, 4)
mml_fused(const float* __restrict__ pred, const int* __restrict__ tgt,
          float* __restrict__ out)
{
    const int b    = blockIdx.x;      // batch
    const int seg  = blockIdx.y;      // row segment
    const int row0 = seg * ROWS;
    const int tid  = threadIdx.x;
    const int lane = tid & 31;
    const int warp = tid >> 5;

    __shared__ int4     cbox[NB];          // compacted boxes: (r0loc, r1loc, y1, y2)
    __shared__ int      s_nbox;
    __shared__ unsigned mask[ROWS * 16];   // 512 column-bits per row
    __shared__ float    red[3][NT / 32];
    __shared__ float    shl[64];
    __shared__ bool     isLast;

    if (tid == 0) s_nbox = 0;
    __syncthreads();

    // ---- compact boxes intersecting this segment (one-time, cheap) ----
    const int4* tb = (const int4*)(tgt + (size_t)b * NB * 4);
    if (tid < NB) {
        int4 bx = tb[tid];
        int x1 = min(bx.x, 512),        y1 = min(bx.y, 512);
        int x2 = min(bx.x + bx.z, 512), y2 = min(bx.y + bx.w, 512);
        if (x2 > row0 && x1 < row0 + ROWS && y2 > y1) {
            int slot = atomicAdd(&s_nbox, 1);
            cbox[slot] = make_int4(max(x1 - row0, 0), min(x2 - row0, ROWS), y1, y2);
        }
    }
    __syncthreads();
    const int nbox = s_nbox;

    // ---- register paint: thread exclusively owns word (tid&15) of rows [4*(tid>>4), +4) ----
    // No atomics, no RMW, no races: each (row, word) cell has exactly one owner.
    {
        const int w       = tid & 15;
        const int rbase   = (tid >> 4) * 4;
        const int colBase = w * 32;
        unsigned m0 = 0, m1 = 0, m2 = 0, m3 = 0;
        for (int i = 0; i < nbox; i++) {
            int4 bx = cbox[i];                       // LDS.128 broadcast
            int lo = min(max(bx.z - colBase, 0), 32);
            int hi = min(max(bx.w - colBase, 0), 32);
            unsigned bits = (unsigned)((1ull << hi) - (1ull << lo));
            int r0 = bx.x, r1 = bx.y;
            m0 |= (rbase + 0 >= r0 && rbase + 0 < r1) ? bits : 0u;
            m1 |= (rbase + 1 >= r0 && rbase + 1 < r1) ? bits : 0u;
            m2 |= (rbase + 2 >= r0 && rbase + 2 < r1) ? bits : 0u;
            m3 |= (rbase + 3 >= r0 && rbase + 3 < r1) ? bits : 0u;
        }
        mask[(rbase + 0) * 16 + w] = m0;
        mask[(rbase + 1) * 16 + w] = m1;
        mask[(rbase + 2) * 16 + w] = m2;
        mask[(rbase + 3) * 16 + w] = m3;
    }
    __syncthreads();

    // ---- streaming reduction over this CTA's 64x512 tile ----
    // idx strides by 256; 256 % 128 == 0 -> column position is loop-invariant.
    float psum = 0.f, isum = 0.f, cnt = 0.f;
    const float4* p = (const float4*)(pred + ((size_t)b * 512 + row0) * 512);
    const int c4   = tid & 127;
    const int wofs = c4 >> 3;
    const int msh  = (c4 & 7) * 4;
    int r = tid >> 7;                         // 0 or 1; +2 per iteration
    #pragma unroll 8
    for (int k = 0; k < 32; k++) {
        float4 v = p[tid + NT * k];
        float s0 = sigf(v.x), s1 = sigf(v.y), s2 = sigf(v.z), s3 = sigf(v.w);
        psum += (s0 + s1) + (s2 + s3);
        unsigned mw = (mask[r * 16 + wofs] >> msh) & 0xFu;
        if (mw & 1u) { isum += s0; cnt += 1.f; }
        if (mw & 2u) { isum += s1; cnt += 1.f; }
        if (mw & 4u) { isum += s2; cnt += 1.f; }
        if (mw & 8u) { isum += s3; cnt += 1.f; }
        r += 2;
    }

    // ---- block reduce ----
    #pragma unroll
    for (int off = 16; off; off >>= 1) {
        psum += __shfl_down_sync(0xffffffffu, psum, off);
        isum += __shfl_down_sync(0xffffffffu, isum, off);
        cnt  += __shfl_down_sync(0xffffffffu, cnt,  off);
    }
    if (lane == 0) { red[0][warp] = psum; red[1][warp] = isum; red[2][warp] = cnt; }
    __syncthreads();
    if (tid == 0) {
        float P = 0.f, I = 0.f, C = 0.f;
        #pragma unroll
        for (int w = 0; w < NT / 32; w++) { P += red[0][w]; I += red[1][w]; C += red[2][w]; }
        g_part[b][seg][0] = P;
        g_part[b][seg][1] = I;
        g_part[b][seg][2] = C;
        __threadfence();
        unsigned prev = atomicAdd(&g_count, 1u);
        isLast = (prev == NCTAS - 1);
        if (isLast) g_count = 0;               // self-reset for graph replay
    }
    __syncthreads();

    // ---- last CTA performs the final reduction (fused; kills the 5us launch) ----
    if (isLast) {
        __threadfence();
        if (tid < 64) {
            volatile float* gp = (volatile float*)g_part;
            float P = 0.f, I = 0.f, C = 0.f;
            #pragma unroll
            for (int s = 0; s < RSPLIT; s++) {
                P += gp[(tid * RSPLIT + s) * 4 + 0];
                I += gp[(tid * RSPLIT + s) * 4 + 1];
                C += gp[(tid * RSPLIT + s) * 4 + 2];
            }
            float inter = 255.f * I;
            shl[tid] = (inter + 1.f) / (P + 255.f * C - inter + 1.f);
        }
        __syncthreads();
        #pragma unroll
        for (int off = 32; off; off >>= 1) {
            if (tid < off && tid + off < 64) shl[tid] += shl[tid + off];
            __syncthreads();
        }
        if (tid == 0) out[0] = 1.0f - shl[0] * (1.0f / 64.0f);
    }
}

extern "C" void kernel_launch(void* const* d_in, const int* in_sizes, int n_in,
                              void* d_out, int out_size) {
    const float* pred = (const float*)d_in[0];   // (64,1,512,512) fp32
    const int*   tgt  = (const int*)d_in[1];     // (64,5,32,4) int32
    float* out = (float*)d_out;                  // scalar

    dim3 grid(64, RSPLIT);
    mml_fused<<<grid, NT>>>(pred, tgt, out);
}